// round 15
// baseline (speedup 1.0000x reference)
#include <cuda_runtime.h>
#include <cuda_fp16.h>
#include <cstdint>

// ---------------------------------------------------------------------------
// DirectGCNLayer on GB300 (sm_103a) — R14
//
//   Wc_in  = W_main_in  + W_shared ;  Wc_out = W_main_out + W_shared
//   H      = X @ [Wc_in | Wc_out]              (N x 128, stored FP16)
//   out[t] = C_in[t] *(sum_in  w*H[src][0:64]   + bc_in)
//          + C_out[t]*(sum_out w*H[src][64:128] + bc_out)
//
// GEMM (R14): fp16 HMMA, A split into fp16 hi+lo (2 passes), B single fp16
//   image (W rel err ~2^-12). 128x128 tile, 104KB smem -> 2 CTAs/SM.
// Gather (R14): warp-per-node, BOTH paths interleaved in one loop, 4-wide
//   predicated chunks (no serial tails) -> 8 H-loads in flight per iter.
// ---------------------------------------------------------------------------

#define MAX_N 100000
#define MAX_E 1000000

typedef unsigned long long u64;
typedef unsigned int u32;

#define TSTRIDE 272                      // padded fp16 tile row stride (bytes)
#define AT_BYTES (128 * TSTRIDE)         // 34816 per image

__device__ __half g_H2[(size_t)MAX_N * 128];        // 25.6 MB fp16 H
__device__ float g_bc[128];                         // combined biases [in|out]
__device__ int   g_off_in[MAX_N + 1];
__device__ int   g_off_out[MAX_N + 1];
__device__ __align__(16) u64 g_pk_in[MAX_E];        // {src, w} packed
__device__ __align__(16) u64 g_pk_out[MAX_E];
__device__ __align__(16) unsigned char g_B[AT_BYTES]; // B=Wc^T fp16, padded

// ---- helpers ---------------------------------------------------------------
__device__ __forceinline__ u32 smem_u32(const void* p) {
    u32 a; asm("{ .reg .u64 t; cvta.to.shared.u64 t, %1; cvt.u32.u64 %0, t; }"
               : "=r"(a) : "l"(p));
    return a;
}
#define LDSM_X4(r0, r1, r2, r3, addr) \
    asm volatile("ldmatrix.sync.aligned.m8n8.x4.shared.b16 {%0,%1,%2,%3}, [%4];" \
                 : "=r"(r0), "=r"(r1), "=r"(r2), "=r"(r3) : "r"(addr))
__device__ __forceinline__ void mma_f16(float* c, const u32* a, u32 b0, u32 b1) {
    asm volatile(
        "mma.sync.aligned.m16n8k16.row.col.f32.f16.f16.f32 "
        "{%0,%1,%2,%3}, {%4,%5,%6,%7}, {%8,%9}, {%0,%1,%2,%3};"
        : "+f"(c[0]), "+f"(c[1]), "+f"(c[2]), "+f"(c[3])
        : "r"(a[0]), "r"(a[1]), "r"(a[2]), "r"(a[3]), "r"(b0), "r"(b1));
}
__device__ __forceinline__ void cp_async16(u32 dst, const void* src) {
    asm volatile("cp.async.cg.shared.global [%0], [%1], 16;" :: "r"(dst), "l"(src));
}

// ---------------------------------------------------------------------------
// prep: B[n][k] = Wc[k][n] (n<64: in, n>=64: out) as fp16, padded image.
// Also combined biases.
// ---------------------------------------------------------------------------
__global__ void prep_kernel(const float* __restrict__ Wmi, const float* __restrict__ Wmo,
                            const float* __restrict__ Wsh,
                            const float* __restrict__ bmi, const float* __restrict__ bmo,
                            const float* __restrict__ bsi, const float* __restrict__ bso) {
    int i = blockIdx.x * blockDim.x + threadIdx.x;
    if (i < 128 * 128) {
        int n = i >> 7, k = i & 127;
        float w;
        if (n < 64) w = Wmi[k * 64 + n] + Wsh[k * 64 + n];
        else        w = Wmo[k * 64 + (n - 64)] + Wsh[k * 64 + (n - 64)];
        *(__half*)(g_B + n * TSTRIDE + k * 2) = __float2half_rn(w);
    }
    if (i < 64) {
        g_bc[i]      = bmi[i] + bsi[i];
        g_bc[64 + i] = bmo[i] + bso[i];
    }
}

// ---------------------------------------------------------------------------
// edges: CSR offsets (off[t] = first e with tgt[e] >= t) AND {src,w} packing.
// ---------------------------------------------------------------------------
__global__ void edges_kernel(const int* __restrict__ si, const float* __restrict__ wi,
                             const int* __restrict__ ti, int Ein,
                             const int* __restrict__ so, const float* __restrict__ wo,
                             const int* __restrict__ to, int Eout, int N) {
    int e = blockIdx.x * blockDim.x + threadIdx.x;
    if (e < Ein)
        g_pk_in[e] = (u64)(u32)__ldg(&si[e]) | ((u64)__float_as_uint(__ldg(&wi[e])) << 32);
    if (e < Eout)
        g_pk_out[e] = (u64)(u32)__ldg(&so[e]) | ((u64)__float_as_uint(__ldg(&wo[e])) << 32);
    if (e <= Ein) {
        int cur  = (e < Ein) ? ti[e]     : N;
        int prev = (e > 0)   ? ti[e - 1] : -1;
        for (int t = prev + 1; t <= cur; ++t) g_off_in[t] = e;
    }
    if (e <= Eout) {
        int cur  = (e < Eout) ? to[e]     : N;
        int prev = (e > 0)    ? to[e - 1] : -1;
        for (int t = prev + 1; t <= cur; ++t) g_off_out[t] = e;
    }
}

// ---------------------------------------------------------------------------
// fp16 HMMA GEMM, A-split 2-pass: H = Ahi@B + Alo@B.
// 128 rows x 128 cols per CTA, 8 warps (wr=wid&3 rows, wc=wid>>2 cols*64).
// SMEM: Ahi | Alo | B  (34816 B each) = 104448 -> 2 CTAs/SM.
// ---------------------------------------------------------------------------
#define SA_HI 0
#define SA_LO AT_BYTES
#define SB    (2 * AT_BYTES)
#define GEMM_SMEM (3 * AT_BYTES)        // 104448

__global__ __launch_bounds__(256, 2) void gemm_kernel(const float* __restrict__ X, int N) {
    extern __shared__ __align__(16) char smem[];
    u32 sb = smem_u32(smem);
    int tid = threadIdx.x;
    int wid = tid >> 5;
    int lane = tid & 31;
    int node0 = blockIdx.x * 128;

    // async copy of B image (overlaps with X convert below)
    {
        const char* bsrc = (const char*)g_B;
        #pragma unroll
        for (int i = tid; i < AT_BYTES / 16; i += 256)
            cp_async16(sb + SB + i * 16, bsrc + i * 16);
        asm volatile("cp.async.commit_group;");
    }

    // load X rows (128), split to fp16 hi/lo, store padded. 2 threads/row.
    {
        int r = tid >> 1, h = tid & 1;
        int n = node0 + r;
        const float4* xrow = (const float4*)(X + (size_t)n * 128);
        char* ahp = smem + SA_HI + r * TSTRIDE;
        char* alp = smem + SA_LO + r * TSTRIDE;
        #pragma unroll
        for (int kk = 0; kk < 16; ++kk) {
            int k4 = h * 16 + kk;             // float4 index; k = 4*k4
            float4 v = (n < N) ? __ldg(&xrow[k4]) : make_float4(0.f, 0.f, 0.f, 0.f);
            __half h0 = __float2half_rn(v.x);
            __half h1 = __float2half_rn(v.y);
            __half h2 = __float2half_rn(v.z);
            __half h3 = __float2half_rn(v.w);
            u32 hw0 = (u32)__half_as_ushort(h0) | ((u32)__half_as_ushort(h1) << 16);
            u32 hw1 = (u32)__half_as_ushort(h2) | ((u32)__half_as_ushort(h3) << 16);
            __half l0 = __float2half_rn(v.x - __half2float(h0));
            __half l1 = __float2half_rn(v.y - __half2float(h1));
            __half l2 = __float2half_rn(v.z - __half2float(h2));
            __half l3 = __float2half_rn(v.w - __half2float(h3));
            u32 lw0 = (u32)__half_as_ushort(l0) | ((u32)__half_as_ushort(l1) << 16);
            u32 lw1 = (u32)__half_as_ushort(l2) | ((u32)__half_as_ushort(l3) << 16);
            *(u64*)(ahp + k4 * 8) = (u64)hw0 | ((u64)hw1 << 32);
            *(u64*)(alp + k4 * 8) = (u64)lw0 | ((u64)lw1 << 32);
        }
    }
    asm volatile("cp.async.wait_group 0;" ::: "memory");
    __syncthreads();

    int wr = wid & 3;      // rows wr*32..+31
    int wc = wid >> 2;     // cols wc*64..+63

    u32 aHi[2], aLo[2];
    #pragma unroll
    for (int mt = 0; mt < 2; ++mt) {
        int row = wr * 32 + mt * 16 + (lane & 15);
        int kb = 16 * (lane >> 4);
        aHi[mt] = sb + SA_HI + row * TSTRIDE + kb;
        aLo[mt] = sb + SA_LO + row * TSTRIDE + kb;
    }
    u32 bB[4];
    #pragma unroll
    for (int p = 0; p < 4; ++p) {
        int nrow = wc * 64 + p * 16 + ((lane >> 4) << 3) + (lane & 7);
        int kb = 16 * ((lane >> 3) & 1);
        bB[p] = sb + SB + nrow * TSTRIDE + kb;
    }

    float c[2][8][4];
    #pragma unroll
    for (int mt = 0; mt < 2; ++mt)
        #pragma unroll
        for (int nt = 0; nt < 8; ++nt)
            #pragma unroll
            for (int q = 0; q < 4; ++q) c[mt][nt][q] = 0.f;

    #pragma unroll
    for (int ks = 0; ks < 8; ++ks) {
        int kb = ks * 32;
        u32 ah[2][4], al[2][4];
        #pragma unroll
        for (int mt = 0; mt < 2; ++mt) {
            LDSM_X4(ah[mt][0], ah[mt][1], ah[mt][2], ah[mt][3], aHi[mt] + kb);
            LDSM_X4(al[mt][0], al[mt][1], al[mt][2], al[mt][3], aLo[mt] + kb);
        }
        u32 bf[4][4];
        #pragma unroll
        for (int p = 0; p < 4; ++p)
            LDSM_X4(bf[p][0], bf[p][1], bf[p][2], bf[p][3], bB[p] + kb);
        #pragma unroll
        for (int mt = 0; mt < 2; ++mt)
            #pragma unroll
            for (int p = 0; p < 4; ++p) {
                mma_f16(c[mt][2 * p],     ah[mt], bf[p][0], bf[p][1]);
                mma_f16(c[mt][2 * p + 1], ah[mt], bf[p][2], bf[p][3]);
                mma_f16(c[mt][2 * p],     al[mt], bf[p][0], bf[p][1]);
                mma_f16(c[mt][2 * p + 1], al[mt], bf[p][2], bf[p][3]);
            }
    }

    // epilogue: d0,d1 -> row lane/4, cols (lane%4)*2; d2,d3 -> row +8.
    #pragma unroll
    for (int mt = 0; mt < 2; ++mt) {
        int row0 = node0 + wr * 32 + mt * 16 + (lane >> 2);
        #pragma unroll
        for (int hf = 0; hf < 2; ++hf) {
            int row = row0 + hf * 8;
            if (row < N) {
                u32* Hp = (u32*)g_H2 + (size_t)row * 64 + wc * 32 + (lane & 3);
                #pragma unroll
                for (int nt = 0; nt < 8; ++nt) {
                    __half2 v = __float22half2_rn(
                        make_float2(c[mt][nt][hf * 2], c[mt][nt][hf * 2 + 1]));
                    Hp[nt * 4] = *(u32*)&v;
                }
            }
        }
    }
}

// ---------------------------------------------------------------------------
// Pull gather: ONE WARP per target node, lane = channel pair. Both paths
// interleaved; 4-wide predicated chunks (weight=0 for OOB) -> no serial
// tails, 8 H-loads in flight per iteration.
// ---------------------------------------------------------------------------
__global__ __launch_bounds__(256) void gather_kernel(
        const float* __restrict__ Cin, const float* __restrict__ Cout,
        float* __restrict__ out, int N) {
    int gid = blockIdx.x * blockDim.x + threadIdx.x;
    int t = gid >> 5;
    if (t >= N) return;
    int l = gid & 31;                  // u32 lane within row half; chans (2l,2l+1)

    int lo_i = g_off_in[t],  hi_i = g_off_in[t + 1];
    int lo_o = g_off_out[t], hi_o = g_off_out[t + 1];
    int ni = hi_i - lo_i, no = hi_o - lo_o;
    int fb_i = (ni > 0) ? hi_i - 1 : 0;    // clamp index for predicated loads
    int fb_o = (no > 0) ? hi_o - 1 : 0;

    const u32* Hin  = (const u32*)g_H2 + l;
    const u32* Hout = (const u32*)g_H2 + 32 + l;

    float ax = 0.f, ay = 0.f, ox = 0.f, oy = 0.f;

    int ci4 = (ni + 3) >> 2, co4 = (no + 3) >> 2;
    int iters = ci4 > co4 ? ci4 : co4;

    for (int it = 0; it < iters; ++it) {
        int ei = lo_i + it * 4;
        int eo = lo_o + it * 4;
        // issue all 8 edge loads (clamped), then all 8 H loads, then math
        u64 pi[4], po[4];
        #pragma unroll
        for (int j = 0; j < 4; ++j) {
            int e1 = ei + j; pi[j] = __ldg(&g_pk_in [(e1 < hi_i) ? e1 : fb_i]);
            int e2 = eo + j; po[j] = __ldg(&g_pk_out[(e2 < hi_o) ? e2 : fb_o]);
        }
        u32 hi4[4], ho4[4];
        #pragma unroll
        for (int j = 0; j < 4; ++j) {
            hi4[j] = __ldg(&Hin [(u32)(u32)pi[j] * 64u]);
            ho4[j] = __ldg(&Hout[(u32)(u32)po[j] * 64u]);
        }
        #pragma unroll
        for (int j = 0; j < 4; ++j) {
            float fi = (ei + j < hi_i) ? __uint_as_float((u32)(pi[j] >> 32)) : 0.f;
            float fo = (eo + j < hi_o) ? __uint_as_float((u32)(po[j] >> 32)) : 0.f;
            float2 vi = __half22float2(*(const __half2*)&hi4[j]);
            float2 vo = __half22float2(*(const __half2*)&ho4[j]);
            ax += fi * vi.x; ay += fi * vi.y;
            ox += fo * vo.x; oy += fo * vo.y;
        }
    }

    int l2 = l * 2;
    float ci = __ldg(&Cin[t]), co = __ldg(&Cout[t]);
    float2 r;
    r.x = ci * (ax + g_bc[l2])     + co * (ox + g_bc[64 + l2]);
    r.y = ci * (ay + g_bc[l2 + 1]) + co * (oy + g_bc[65 + l2]);
    *(float2*)&out[(size_t)t * 64 + l2] = r;
}

// ---------------------------------------------------------------------------
extern "C" void kernel_launch(void* const* d_in, const int* in_sizes, int n_in,
                              void* d_out, int out_size) {
    const float* x    = (const float*)d_in[0];
    const float* Wmi  = (const float*)d_in[1];
    const float* Wmo  = (const float*)d_in[2];
    const float* Wsh  = (const float*)d_in[3];
    const float* bmi  = (const float*)d_in[4];
    const float* bmo  = (const float*)d_in[5];
    const float* bsi  = (const float*)d_in[6];
    const float* bso  = (const float*)d_in[7];
    const float* Cin  = (const float*)d_in[8];
    const float* Cout = (const float*)d_in[9];
    const int*   ei_in  = (const int*)d_in[10];
    const float* ew_in  = (const float*)d_in[11];
    const int*   ei_out = (const int*)d_in[12];
    const float* ew_out = (const float*)d_in[13];

    int N    = in_sizes[0] / 128;
    int Ein  = in_sizes[10] / 2;
    int Eout = in_sizes[12] / 2;
    float* out = (float*)d_out;

    int Emax = (Ein > Eout ? Ein : Eout);

    cudaFuncSetAttribute(gemm_kernel, cudaFuncAttributeMaxDynamicSharedMemorySize,
                         GEMM_SMEM);

    prep_kernel<<<64, 256>>>(Wmi, Wmo, Wsh, bmi, bmo, bsi, bso);
    edges_kernel<<<(Emax + 1 + 255) / 256, 256>>>(
        ei_in, ew_in, ei_in + Ein, Ein,
        ei_out, ew_out, ei_out + Eout, Eout, N);
    gemm_kernel<<<(N + 127) / 128, 256, GEMM_SMEM>>>(x, N);
    gather_kernel<<<((size_t)N * 32 + 255) / 256, 256>>>(Cin, Cout, out, N);
}

// round 17
// speedup vs baseline: 1.0524x; 1.0524x over previous
#include <cuda_runtime.h>
#include <cuda_fp16.h>
#include <cstdint>

// ---------------------------------------------------------------------------
// DirectGCNLayer on GB300 (sm_103a) — R17 (R16 re-bench; container died)
//
//   Wc_in  = W_main_in  + W_shared ;  Wc_out = W_main_out + W_shared
//   H      = X @ [Wc_in | Wc_out]              (N x 128, stored FP16)
//   out[t] = C_in[t] *(sum_in  w*H[src][0:64]   + bc_in)
//          + C_out[t]*(sum_out w*H[src][64:128] + bc_out)
//
// GEMM: fp16 HMMA m16n8k16, A split hi+lo (2 passes), single fp16 B image.
//   128x128 tile, 104KB smem -> 2 CTAs/SM, cp.async B copy.
// Gather: R13 per-path loop shape (R15's predication regressed: issue-bound,
//   not latency-bound). Packed edges carry PRE-SCALED byte offsets
//   {w_f32 : src*256} so each H address is one 32-bit IADD, no IMAD chain.
// ---------------------------------------------------------------------------

#define MAX_N 100000
#define MAX_E 1000000

typedef unsigned long long u64;
typedef unsigned int u32;

#define TSTRIDE 272                      // padded fp16 tile row stride (bytes)
#define AT_BYTES (128 * TSTRIDE)         // 34816 per image

__device__ __half g_H2[(size_t)MAX_N * 128];        // 25.6 MB fp16 H
__device__ float g_bc[128];                         // combined biases [in|out]
__device__ int   g_off_in[MAX_N + 1];
__device__ int   g_off_out[MAX_N + 1];
__device__ __align__(16) u64 g_pk_in[MAX_E];        // {w_f32 : src*256}
__device__ __align__(16) u64 g_pk_out[MAX_E];
__device__ __align__(16) unsigned char g_B[AT_BYTES]; // B=Wc^T fp16, padded

// ---- helpers ---------------------------------------------------------------
__device__ __forceinline__ u32 smem_u32(const void* p) {
    u32 a; asm("{ .reg .u64 t; cvta.to.shared.u64 t, %1; cvt.u32.u64 %0, t; }"
               : "=r"(a) : "l"(p));
    return a;
}
#define LDSM_X4(r0, r1, r2, r3, addr) \
    asm volatile("ldmatrix.sync.aligned.m8n8.x4.shared.b16 {%0,%1,%2,%3}, [%4];" \
                 : "=r"(r0), "=r"(r1), "=r"(r2), "=r"(r3) : "r"(addr))
__device__ __forceinline__ void mma_f16(float* c, const u32* a, u32 b0, u32 b1) {
    asm volatile(
        "mma.sync.aligned.m16n8k16.row.col.f32.f16.f16.f32 "
        "{%0,%1,%2,%3}, {%4,%5,%6,%7}, {%8,%9}, {%0,%1,%2,%3};"
        : "+f"(c[0]), "+f"(c[1]), "+f"(c[2]), "+f"(c[3])
        : "r"(a[0]), "r"(a[1]), "r"(a[2]), "r"(a[3]), "r"(b0), "r"(b1));
}
__device__ __forceinline__ void cp_async16(u32 dst, const void* src) {
    asm volatile("cp.async.cg.shared.global [%0], [%1], 16;" :: "r"(dst), "l"(src));
}

// ---------------------------------------------------------------------------
// prep: B[n][k] = Wc[k][n] (n<64: in, n>=64: out) as fp16, padded image.
// Also combined biases.
// ---------------------------------------------------------------------------
__global__ void prep_kernel(const float* __restrict__ Wmi, const float* __restrict__ Wmo,
                            const float* __restrict__ Wsh,
                            const float* __restrict__ bmi, const float* __restrict__ bmo,
                            const float* __restrict__ bsi, const float* __restrict__ bso) {
    int i = blockIdx.x * blockDim.x + threadIdx.x;
    if (i < 128 * 128) {
        int n = i >> 7, k = i & 127;
        float w;
        if (n < 64) w = Wmi[k * 64 + n] + Wsh[k * 64 + n];
        else        w = Wmo[k * 64 + (n - 64)] + Wsh[k * 64 + (n - 64)];
        *(__half*)(g_B + n * TSTRIDE + k * 2) = __float2half_rn(w);
    }
    if (i < 64) {
        g_bc[i]      = bmi[i] + bsi[i];
        g_bc[64 + i] = bmo[i] + bso[i];
    }
}

// ---------------------------------------------------------------------------
// edges: CSR offsets (off[t] = first e with tgt[e] >= t) AND packing
// {w : src*256} (byte offset of the fp16 H row) for both lists.
// src<<8 <= 100000*256 = 25.6M fits u32.
// ---------------------------------------------------------------------------
__global__ void edges_kernel(const int* __restrict__ si, const float* __restrict__ wi,
                             const int* __restrict__ ti, int Ein,
                             const int* __restrict__ so, const float* __restrict__ wo,
                             const int* __restrict__ to, int Eout, int N) {
    int e = blockIdx.x * blockDim.x + threadIdx.x;
    if (e < Ein)
        g_pk_in[e] = (u64)((u32)__ldg(&si[e]) << 8)
                   | ((u64)__float_as_uint(__ldg(&wi[e])) << 32);
    if (e < Eout)
        g_pk_out[e] = (u64)((u32)__ldg(&so[e]) << 8)
                    | ((u64)__float_as_uint(__ldg(&wo[e])) << 32);
    if (e <= Ein) {
        int cur  = (e < Ein) ? ti[e]     : N;
        int prev = (e > 0)   ? ti[e - 1] : -1;
        for (int t = prev + 1; t <= cur; ++t) g_off_in[t] = e;
    }
    if (e <= Eout) {
        int cur  = (e < Eout) ? to[e]     : N;
        int prev = (e > 0)    ? to[e - 1] : -1;
        for (int t = prev + 1; t <= cur; ++t) g_off_out[t] = e;
    }
}

// ---------------------------------------------------------------------------
// fp16 HMMA GEMM, A-split 2-pass: H = Ahi@B + Alo@B.
// 128 rows x 128 cols per CTA, 8 warps (wr=wid&3 rows, wc=wid>>2 cols*64).
// SMEM: Ahi | Alo | B  (34816 B each) = 104448 -> 2 CTAs/SM.
// ---------------------------------------------------------------------------
#define SA_HI 0
#define SA_LO AT_BYTES
#define SB    (2 * AT_BYTES)
#define GEMM_SMEM (3 * AT_BYTES)        // 104448

__global__ __launch_bounds__(256, 2) void gemm_kernel(const float* __restrict__ X, int N) {
    extern __shared__ __align__(16) char smem[];
    u32 sb = smem_u32(smem);
    int tid = threadIdx.x;
    int wid = tid >> 5;
    int lane = tid & 31;
    int node0 = blockIdx.x * 128;

    // async copy of B image (overlaps with X convert below)
    {
        const char* bsrc = (const char*)g_B;
        #pragma unroll
        for (int i = tid; i < AT_BYTES / 16; i += 256)
            cp_async16(sb + SB + i * 16, bsrc + i * 16);
        asm volatile("cp.async.commit_group;");
    }

    // load X rows (128), split to fp16 hi/lo, store padded. 2 threads/row.
    {
        int r = tid >> 1, h = tid & 1;
        int n = node0 + r;
        const float4* xrow = (const float4*)(X + (size_t)n * 128);
        char* ahp = smem + SA_HI + r * TSTRIDE;
        char* alp = smem + SA_LO + r * TSTRIDE;
        #pragma unroll
        for (int kk = 0; kk < 16; ++kk) {
            int k4 = h * 16 + kk;             // float4 index; k = 4*k4
            float4 v = (n < N) ? __ldg(&xrow[k4]) : make_float4(0.f, 0.f, 0.f, 0.f);
            __half h0 = __float2half_rn(v.x);
            __half h1 = __float2half_rn(v.y);
            __half h2 = __float2half_rn(v.z);
            __half h3 = __float2half_rn(v.w);
            u32 hw0 = (u32)__half_as_ushort(h0) | ((u32)__half_as_ushort(h1) << 16);
            u32 hw1 = (u32)__half_as_ushort(h2) | ((u32)__half_as_ushort(h3) << 16);
            __half l0 = __float2half_rn(v.x - __half2float(h0));
            __half l1 = __float2half_rn(v.y - __half2float(h1));
            __half l2 = __float2half_rn(v.z - __half2float(h2));
            __half l3 = __float2half_rn(v.w - __half2float(h3));
            u32 lw0 = (u32)__half_as_ushort(l0) | ((u32)__half_as_ushort(l1) << 16);
            u32 lw1 = (u32)__half_as_ushort(l2) | ((u32)__half_as_ushort(l3) << 16);
            *(u64*)(ahp + k4 * 8) = (u64)hw0 | ((u64)hw1 << 32);
            *(u64*)(alp + k4 * 8) = (u64)lw0 | ((u64)lw1 << 32);
        }
    }
    asm volatile("cp.async.wait_group 0;" ::: "memory");
    __syncthreads();

    int wr = wid & 3;      // rows wr*32..+31
    int wc = wid >> 2;     // cols wc*64..+63

    u32 aHi[2], aLo[2];
    #pragma unroll
    for (int mt = 0; mt < 2; ++mt) {
        int row = wr * 32 + mt * 16 + (lane & 15);
        int kb = 16 * (lane >> 4);
        aHi[mt] = sb + SA_HI + row * TSTRIDE + kb;
        aLo[mt] = sb + SA_LO + row * TSTRIDE + kb;
    }
    u32 bB[4];
    #pragma unroll
    for (int p = 0; p < 4; ++p) {
        int nrow = wc * 64 + p * 16 + ((lane >> 4) << 3) + (lane & 7);
        int kb = 16 * ((lane >> 3) & 1);
        bB[p] = sb + SB + nrow * TSTRIDE + kb;
    }

    float c[2][8][4];
    #pragma unroll
    for (int mt = 0; mt < 2; ++mt)
        #pragma unroll
        for (int nt = 0; nt < 8; ++nt)
            #pragma unroll
            for (int q = 0; q < 4; ++q) c[mt][nt][q] = 0.f;

    #pragma unroll
    for (int ks = 0; ks < 8; ++ks) {
        int kb = ks * 32;
        u32 ah[2][4], al[2][4];
        #pragma unroll
        for (int mt = 0; mt < 2; ++mt) {
            LDSM_X4(ah[mt][0], ah[mt][1], ah[mt][2], ah[mt][3], aHi[mt] + kb);
            LDSM_X4(al[mt][0], al[mt][1], al[mt][2], al[mt][3], aLo[mt] + kb);
        }
        u32 bf[4][4];
        #pragma unroll
        for (int p = 0; p < 4; ++p)
            LDSM_X4(bf[p][0], bf[p][1], bf[p][2], bf[p][3], bB[p] + kb);
        #pragma unroll
        for (int mt = 0; mt < 2; ++mt)
            #pragma unroll
            for (int p = 0; p < 4; ++p) {
                mma_f16(c[mt][2 * p],     ah[mt], bf[p][0], bf[p][1]);
                mma_f16(c[mt][2 * p + 1], ah[mt], bf[p][2], bf[p][3]);
                mma_f16(c[mt][2 * p],     al[mt], bf[p][0], bf[p][1]);
                mma_f16(c[mt][2 * p + 1], al[mt], bf[p][2], bf[p][3]);
            }
    }

    // epilogue: d0,d1 -> row lane/4, cols (lane%4)*2; d2,d3 -> row +8.
    #pragma unroll
    for (int mt = 0; mt < 2; ++mt) {
        int row0 = node0 + wr * 32 + mt * 16 + (lane >> 2);
        #pragma unroll
        for (int hf = 0; hf < 2; ++hf) {
            int row = row0 + hf * 8;
            if (row < N) {
                u32* Hp = (u32*)g_H2 + (size_t)row * 64 + wc * 32 + (lane & 3);
                #pragma unroll
                for (int nt = 0; nt < 8; ++nt) {
                    __half2 v = __float22half2_rn(
                        make_float2(c[mt][nt][hf * 2], c[mt][nt][hf * 2 + 1]));
                    Hp[nt * 4] = *(u32*)&v;
                }
            }
        }
    }
}

// ---------------------------------------------------------------------------
// Pull gather: ONE WARP per target node, lane = channel pair (2l, 2l+1).
// Per-path loops, unroll 4 (LDG.128 = 2 packed edges). H address = one IADD
// (offsets pre-scaled to bytes in the packed word). fp32 accumulation.
// ---------------------------------------------------------------------------
__global__ __launch_bounds__(256) void gather_kernel(
        const float* __restrict__ Cin, const float* __restrict__ Cout,
        float* __restrict__ out, int N) {
    int gid = blockIdx.x * blockDim.x + threadIdx.x;
    int t = gid >> 5;
    if (t >= N) return;
    int l = gid & 31;                  // u32 lane within row half; chans (2l,2l+1)

    // hoist node-level loads so they overlap the loop
    float ci = __ldg(&Cin[t]), co = __ldg(&Cout[t]);
    int l2 = l * 2;
    float bi0 = g_bc[l2], bi1 = g_bc[l2 + 1];
    float bo0 = g_bc[64 + l2], bo1 = g_bc[65 + l2];

    float ax = 0.f, ay = 0.f, ox = 0.f, oy = 0.f;

    #pragma unroll
    for (int path = 0; path < 2; ++path) {
        int lo = path ? g_off_out[t] : g_off_in[t];
        int hi = path ? g_off_out[t + 1] : g_off_in[t + 1];
        const u64* Pk = path ? g_pk_out : g_pk_in;
        const char* Hb = (const char*)g_H2 + (path ? 128 + l * 4 : l * 4);
        float sx = 0.f, sy = 0.f;
        int e = lo;
        if ((e < hi) && (e & 1)) {
            u64 p = __ldg(&Pk[e]);
            float f = __uint_as_float((u32)(p >> 32));
            u32 h = *(const u32*)(Hb + (u32)p);
            float2 v = __half22float2(*(const __half2*)&h);
            sx += f * v.x; sy += f * v.y;
            ++e;
        }
        const ulonglong2* P2 = (const ulonglong2*)Pk;
        for (; e + 3 < hi; e += 4) {
            ulonglong2 pa = __ldg(&P2[e >> 1]);
            ulonglong2 pb = __ldg(&P2[(e >> 1) + 1]);
            u32 h0 = *(const u32*)(Hb + (u32)pa.x);
            u32 h1 = *(const u32*)(Hb + (u32)pa.y);
            u32 h2 = *(const u32*)(Hb + (u32)pb.x);
            u32 h3 = *(const u32*)(Hb + (u32)pb.y);
            float f0 = __uint_as_float((u32)(pa.x >> 32));
            float f1 = __uint_as_float((u32)(pa.y >> 32));
            float f2 = __uint_as_float((u32)(pb.x >> 32));
            float f3 = __uint_as_float((u32)(pb.y >> 32));
            float2 v0 = __half22float2(*(const __half2*)&h0);
            float2 v1 = __half22float2(*(const __half2*)&h1);
            float2 v2 = __half22float2(*(const __half2*)&h2);
            float2 v3 = __half22float2(*(const __half2*)&h3);
            sx += f0 * v0.x; sy += f0 * v0.y;
            sx += f1 * v1.x; sy += f1 * v1.y;
            sx += f2 * v2.x; sy += f2 * v2.y;
            sx += f3 * v3.x; sy += f3 * v3.y;
        }
        if (e + 1 < hi) {
            ulonglong2 pa = __ldg(&P2[e >> 1]);
            u32 h0 = *(const u32*)(Hb + (u32)pa.x);
            u32 h1 = *(const u32*)(Hb + (u32)pa.y);
            float f0 = __uint_as_float((u32)(pa.x >> 32));
            float f1 = __uint_as_float((u32)(pa.y >> 32));
            float2 v0 = __half22float2(*(const __half2*)&h0);
            float2 v1 = __half22float2(*(const __half2*)&h1);
            sx += f0 * v0.x; sy += f0 * v0.y;
            sx += f1 * v1.x; sy += f1 * v1.y;
            e += 2;
        }
        if (e < hi) {
            u64 p = __ldg(&Pk[e]);
            float f = __uint_as_float((u32)(p >> 32));
            u32 h = *(const u32*)(Hb + (u32)p);
            float2 v = __half22float2(*(const __half2*)&h);
            sx += f * v.x; sy += f * v.y;
        }
        if (path) { ox = sx; oy = sy; } else { ax = sx; ay = sy; }
    }

    float2 r;
    r.x = ci * (ax + bi0) + co * (ox + bo0);
    r.y = ci * (ay + bi1) + co * (oy + bo1);
    *(float2*)&out[(size_t)t * 64 + l2] = r;
}

// ---------------------------------------------------------------------------
extern "C" void kernel_launch(void* const* d_in, const int* in_sizes, int n_in,
                              void* d_out, int out_size) {
    const float* x    = (const float*)d_in[0];
    const float* Wmi  = (const float*)d_in[1];
    const float* Wmo  = (const float*)d_in[2];
    const float* Wsh  = (const float*)d_in[3];
    const float* bmi  = (const float*)d_in[4];
    const float* bmo  = (const float*)d_in[5];
    const float* bsi  = (const float*)d_in[6];
    const float* bso  = (const float*)d_in[7];
    const float* Cin  = (const float*)d_in[8];
    const float* Cout = (const float*)d_in[9];
    const int*   ei_in  = (const int*)d_in[10];
    const float* ew_in  = (const float*)d_in[11];
    const int*   ei_out = (const int*)d_in[12];
    const float* ew_out = (const float*)d_in[13];

    int N    = in_sizes[0] / 128;
    int Ein  = in_sizes[10] / 2;
    int Eout = in_sizes[12] / 2;
    float* out = (float*)d_out;

    int Emax = (Ein > Eout ? Ein : Eout);

    cudaFuncSetAttribute(gemm_kernel, cudaFuncAttributeMaxDynamicSharedMemorySize,
                         GEMM_SMEM);

    prep_kernel<<<64, 256>>>(Wmi, Wmo, Wsh, bmi, bmo, bsi, bso);
    edges_kernel<<<(Emax + 1 + 255) / 256, 256>>>(
        ei_in, ew_in, ei_in + Ein, Ein,
        ei_out, ew_out, ei_out + Eout, Eout, N);
    gemm_kernel<<<(N + 127) / 128, 256, GEMM_SMEM>>>(x, N);
    gather_kernel<<<((size_t)N * 32 + 255) / 256, 256>>>(Cin, Cout, out, N);
}